// round 16
// baseline (speedup 1.0000x reference)
#include <cuda_runtime.h>
#include <cuda_fp16.h>
#include <cstdint>

// LightGCN: 3 layers of SpMM + running-mean accumulator.
// N=400000 nodes, D=64, E=4000000 edges.
// out = (x0 + x1 + x2 + x3) / 4, x_{k+1} = A @ x_k (A sparse COO, fp32 vals)
//
// R14 structure (CSR build, emb->fp16, 8-threads/row unroll-x4 SpMM, fused
// final mean) + degree-sorted row permutation so the 4 rows sharing a warp
// have near-equal degree (kills max-of-4 divergence waste).

#define NUM_NODES 400000
#define EMB_DIM   64
#define NELEM     (NUM_NODES * EMB_DIM)   // 25,600,000
#define MAX_EDGES 4000000
#define SCAN_BLK  512
#define NB_SCAN   ((NUM_NODES + SCAN_BLK - 1) / SCAN_BLK)   // 782
#define NBUCKET   64

// fp16 buffers (51.2 MB each): h0 = emb_fp16, h1/h2 ping-pong
__device__ __half g_h0[NELEM];
__device__ __half g_h1[NELEM];
__device__ __half g_h2[NELEM];

// CSR scratch
__device__ int  g_cnt[NUM_NODES];
__device__ int  g_rowptr[NUM_NODES];
__device__ int  g_ofs[NUM_NODES];
__device__ int  g_part[1024];
__device__ int2 g_edge[MAX_EDGES];     // {col, val_bits}
__device__ int  g_is64;

// degree bucketing -> row permutation
__device__ int  g_bucket[NBUCKET];     // counts -> (scanB) offsets cursor
__device__ int  g_perm[NUM_NODES];

// ---------------------------------------------------------------------------
// dtype detect: int64 indices have all-zero high words (indices < 400000).
// ---------------------------------------------------------------------------
__global__ void detect_kernel(const unsigned int* __restrict__ raw) {
    __shared__ unsigned int s;
    if (threadIdx.x == 0) s = 0u;
    __syncthreads();
    unsigned int acc = 0u;
    for (int i = threadIdx.x; i < 1024; i += blockDim.x)
        acc |= raw[2 * i + 1];
    atomicOr(&s, acc);
    __syncthreads();
    if (threadIdx.x == 0) g_is64 = (s == 0u) ? 1 : 0;
}

__global__ void zero_cnt_kernel() {
    int i = blockIdx.x * blockDim.x + threadIdx.x;
    if (i < NUM_NODES) g_cnt[i] = 0;
    if (i < NBUCKET)   g_bucket[i] = 0;
}

__global__ void hist_kernel(const unsigned int* __restrict__ row_raw,
                            int n_edges) {
    int e = blockIdx.x * blockDim.x + threadIdx.x;
    if (e >= n_edges) return;
    int idx = g_is64 ? (2 * e) : e;
    atomicAdd(&g_cnt[(int)row_raw[idx]], 1);
}

// ---------------------------------------------------------------------------
// two-level exclusive scan of g_cnt -> g_rowptr (and g_ofs copy)
// ---------------------------------------------------------------------------
__global__ void scanA_kernel() {
    __shared__ int sh[SCAN_BLK];
    int tid = threadIdx.x;
    int gid = blockIdx.x * SCAN_BLK + tid;
    int v = (gid < NUM_NODES) ? g_cnt[gid] : 0;
    sh[tid] = v;
    __syncthreads();
    for (int off = 1; off < SCAN_BLK; off <<= 1) {
        int t = (tid >= off) ? sh[tid - off] : 0;
        __syncthreads();
        if (tid >= off) sh[tid] += t;
        __syncthreads();
    }
    if (gid < NUM_NODES) g_rowptr[gid] = sh[tid] - v;
    if (tid == SCAN_BLK - 1) g_part[blockIdx.x] = sh[tid];
}

__global__ void scanB_kernel() {
    __shared__ int sh[1024];
    int tid = threadIdx.x;
    int v = (tid < NB_SCAN) ? g_part[tid] : 0;
    sh[tid] = v;
    __syncthreads();
    for (int off = 1; off < 1024; off <<= 1) {
        int t = (tid >= off) ? sh[tid - off] : 0;
        __syncthreads();
        if (tid >= off) sh[tid] += t;
        __syncthreads();
    }
    if (tid < NB_SCAN) g_part[tid] = sh[tid] - v;
}

__global__ void scanC_kernel() {
    int i = blockIdx.x * blockDim.x + threadIdx.x;
    if (i >= NUM_NODES) return;
    int rp = g_rowptr[i] + g_part[i / SCAN_BLK];
    g_rowptr[i] = rp;
    g_ofs[i]    = rp;
}

__global__ void scatter_kernel(const unsigned int* __restrict__ row_raw,
                               const unsigned int* __restrict__ col_raw,
                               const float* __restrict__ val,
                               int n_edges) {
    int e = blockIdx.x * blockDim.x + threadIdx.x;
    if (e >= n_edges) return;
    int idx = g_is64 ? (2 * e) : e;
    int r = (int)row_raw[idx];
    int c = (int)col_raw[idx];
    int pos = atomicAdd(&g_ofs[r], 1);
    g_edge[pos] = make_int2(c, __float_as_int(val[e]));
}

// ---------------------------------------------------------------------------
// degree bucketing: count per clamped-degree bucket, scan 64 buckets,
// place rows -> g_perm (rows grouped by degree; warp's 4 rows ~equal deg)
// ---------------------------------------------------------------------------
__global__ void bucket_count_kernel() {
    int i = blockIdx.x * blockDim.x + threadIdx.x;
    if (i >= NUM_NODES) return;
    int b = min(g_cnt[i], NBUCKET - 1);
    atomicAdd(&g_bucket[b], 1);
}

__global__ void bucket_scan_kernel() {    // 1 block, 64 threads
    __shared__ int sh[NBUCKET];
    int tid = threadIdx.x;
    int v = g_bucket[tid];
    sh[tid] = v;
    __syncthreads();
    for (int off = 1; off < NBUCKET; off <<= 1) {
        int t = (tid >= off) ? sh[tid - off] : 0;
        __syncthreads();
        if (tid >= off) sh[tid] += t;
        __syncthreads();
    }
    g_bucket[tid] = sh[tid] - v;   // exclusive offsets, doubles as cursor
}

__global__ void bucket_place_kernel() {
    int i = blockIdx.x * blockDim.x + threadIdx.x;
    if (i >= NUM_NODES) return;
    int b = min(g_cnt[i], NBUCKET - 1);
    int pos = atomicAdd(&g_bucket[b], 1);
    g_perm[pos] = i;
}

// ---------------------------------------------------------------------------
// emb fp32 -> fp16 conversion, 8 floats per thread, float4 I/O
// ---------------------------------------------------------------------------
__global__ void conv_kernel(const float4* __restrict__ src,
                            float4* __restrict__ dst) {   // dst = half buffer
    int i = blockIdx.x * blockDim.x + threadIdx.x;        // 8-float chunk idx
    if (i >= NELEM / 8) return;
    float4 a = src[2 * i];
    float4 b = src[2 * i + 1];
    float4 r;
    __half2* h = reinterpret_cast<__half2*>(&r);
    h[0] = __float22half2_rn(make_float2(a.x, a.y));
    h[1] = __float22half2_rn(make_float2(a.z, a.w));
    h[2] = __float22half2_rn(make_float2(b.x, b.y));
    h[3] = __float22half2_rn(make_float2(b.z, b.w));
    dst[i] = r;
}

// ---------------------------------------------------------------------------
// helpers
// ---------------------------------------------------------------------------
__device__ __forceinline__ float4 pack8h(const float* a) {
    float4 r;
    __half2* h = reinterpret_cast<__half2*>(&r);
    h[0] = __float22half2_rn(make_float2(a[0], a[1]));
    h[1] = __float22half2_rn(make_float2(a[2], a[3]));
    h[2] = __float22half2_rn(make_float2(a[4], a[5]));
    h[3] = __float22half2_rn(make_float2(a[6], a[7]));
    return r;
}

__device__ __forceinline__ void accum8h(float* a, float4 x, float v) {
    const __half2* h = reinterpret_cast<const __half2*>(&x);
#pragma unroll
    for (int j = 0; j < 4; j++) {
        float2 f = __half22float2(h[j]);
        a[2 * j]     = fmaf(v, f.x, a[2 * j]);
        a[2 * j + 1] = fmaf(v, f.y, a[2 * j + 1]);
    }
}

// ---------------------------------------------------------------------------
// fp16-gather SpMM (R14 shape): 8 threads/row, 8 dims (1 float4 of halves)
// per lane, edge loop unrolled x4 (4 independent gathers in flight).
// Rows are taken through g_perm so a warp's 4 rows have ~equal degree.
// mode 0: dst = acc (fp16)
// mode 1: out = 0.25*(emb_fp32 + x1 + x2 + acc)   (fused final mean)
// ---------------------------------------------------------------------------
__global__ void __launch_bounds__(256)
spmm_h_kernel(const __half* __restrict__ src,
              __half* __restrict__ dst,
              const float* __restrict__ emb,
              const __half* __restrict__ x1,
              const __half* __restrict__ x2,
              float* __restrict__ out,
              int final_mode) {
    int t = blockIdx.x * blockDim.x + threadIdx.x;
    int g = t >> 3;
    if (g >= NUM_NODES) return;
    int r   = g_perm[g];       // 8 lanes same addr -> broadcast
    int sub = t & 7;

    int start = g_rowptr[r];
    int deg   = g_cnt[r];

    float a[8];
#pragma unroll
    for (int j = 0; j < 8; j++) a[j] = 0.f;

    const float4* s4 = reinterpret_cast<const float4*>(src);  // 8 halves each

    int i = 0;
    for (; i + 4 <= deg; i += 4) {
        int2 e0 = __ldg(&g_edge[start + i]);
        int2 e1 = __ldg(&g_edge[start + i + 1]);
        int2 e2 = __ldg(&g_edge[start + i + 2]);
        int2 e3 = __ldg(&g_edge[start + i + 3]);
        float4 x0 = __ldg(s4 + (((size_t)e0.x) << 3) + sub);
        float4 x1v= __ldg(s4 + (((size_t)e1.x) << 3) + sub);
        float4 x2v= __ldg(s4 + (((size_t)e2.x) << 3) + sub);
        float4 x3v= __ldg(s4 + (((size_t)e3.x) << 3) + sub);
        accum8h(a, x0,  __int_as_float(e0.y));
        accum8h(a, x1v, __int_as_float(e1.y));
        accum8h(a, x2v, __int_as_float(e2.y));
        accum8h(a, x3v, __int_as_float(e3.y));
    }
    for (; i < deg; i++) {
        int2 e0 = __ldg(&g_edge[start + i]);
        float4 x0 = __ldg(s4 + (((size_t)e0.x) << 3) + sub);
        accum8h(a, x0, __int_as_float(e0.y));
    }

    size_t hofs = ((size_t)r << 3) + sub;        // float4 index, half buffers
    if (!final_mode) {
        reinterpret_cast<float4*>(dst)[hofs] = pack8h(a);
    } else {
        size_t fofs = ((size_t)r << 4) + (sub << 1);  // float4 index, fp32
        const float4* E = reinterpret_cast<const float4*>(emb);
        float4 e0 = __ldg(E + fofs), e1 = __ldg(E + fofs + 1);

        float u[8], w[8];
        {
            float4 xh = __ldg(reinterpret_cast<const float4*>(x1) + hofs);
            const __half2* h = reinterpret_cast<const __half2*>(&xh);
#pragma unroll
            for (int j = 0; j < 4; j++) {
                float2 f = __half22float2(h[j]);
                u[2*j] = f.x; u[2*j+1] = f.y;
            }
        }
        {
            float4 xh = __ldg(reinterpret_cast<const float4*>(x2) + hofs);
            const __half2* h = reinterpret_cast<const __half2*>(&xh);
#pragma unroll
            for (int j = 0; j < 4; j++) {
                float2 f = __half22float2(h[j]);
                w[2*j] = f.x; w[2*j+1] = f.y;
            }
        }

        float4 r0, r1;
        r0.x = 0.25f * (e0.x + u[0] + w[0] + a[0]);
        r0.y = 0.25f * (e0.y + u[1] + w[1] + a[1]);
        r0.z = 0.25f * (e0.z + u[2] + w[2] + a[2]);
        r0.w = 0.25f * (e0.w + u[3] + w[3] + a[3]);
        r1.x = 0.25f * (e1.x + u[4] + w[4] + a[4]);
        r1.y = 0.25f * (e1.y + u[5] + w[5] + a[5]);
        r1.z = 0.25f * (e1.z + u[6] + w[6] + a[6]);
        r1.w = 0.25f * (e1.w + u[7] + w[7] + a[7]);
        reinterpret_cast<float4*>(out)[fofs]     = r0;
        reinterpret_cast<float4*>(out)[fofs + 1] = r1;
    }
}

// ---------------------------------------------------------------------------
// launch
// ---------------------------------------------------------------------------
extern "C" void kernel_launch(void* const* d_in, const int* in_sizes, int n_in,
                              void* d_out, int out_size) {
    // Order-robust binding: embedding is the unique input with NELEM elements;
    // the remaining three, in original order, are row, col, val.
    int emb_idx = -1;
    for (int i = 0; i < n_in; i++)
        if (in_sizes[i] == NELEM) { emb_idx = i; break; }
    if (emb_idx < 0) emb_idx = 0;

    int others[3]; int k = 0;
    for (int i = 0; i < n_in && k < 3; i++)
        if (i != emb_idx) others[k++] = i;

    const float*        emb     = (const float*)d_in[emb_idx];
    const unsigned int* row_raw = (const unsigned int*)d_in[others[0]];
    const unsigned int* col_raw = (const unsigned int*)d_in[others[1]];
    const float*        val     = (const float*)d_in[others[2]];
    float*              out     = (float*)d_out;
    const int n_edges = in_sizes[others[0]];

    __half *h0 = nullptr, *h1 = nullptr, *h2 = nullptr;
    cudaGetSymbolAddress((void**)&h0, g_h0);
    cudaGetSymbolAddress((void**)&h1, g_h1);
    cudaGetSymbolAddress((void**)&h2, g_h2);

    const int TB = 256;
    const int grid_edges = (n_edges + TB - 1) / TB;
    const int grid_nodes = (NUM_NODES + TB - 1) / TB;
    const int grid_conv  = (NELEM / 8 + TB - 1) / TB;
    const int grid_spmm  = (NUM_NODES * 8 + TB - 1) / TB;

    // ---- CSR build + emb fp16 conversion ----
    detect_kernel<<<1, 256>>>(row_raw);
    zero_cnt_kernel<<<grid_nodes, TB>>>();
    hist_kernel<<<grid_edges, TB>>>(row_raw, n_edges);
    conv_kernel<<<grid_conv, TB>>>((const float4*)emb, (float4*)h0);
    scanA_kernel<<<NB_SCAN, SCAN_BLK>>>();
    scanB_kernel<<<1, 1024>>>();
    scanC_kernel<<<grid_nodes, TB>>>();
    scatter_kernel<<<grid_edges, TB>>>(row_raw, col_raw, val, n_edges);

    // ---- degree-sorted row permutation ----
    bucket_count_kernel<<<grid_nodes, TB>>>();
    bucket_scan_kernel<<<1, NBUCKET>>>();
    bucket_place_kernel<<<grid_nodes, TB>>>();

    // ---- 3 propagation layers (8 threads/row, fp16 gathers, perm order) ----
    // layer 1: h0 -> h1
    spmm_h_kernel<<<grid_spmm, TB>>>(h0, h1, nullptr, nullptr, nullptr, nullptr, 0);
    // layer 2: h1 -> h2
    spmm_h_kernel<<<grid_spmm, TB>>>(h1, h2, nullptr, nullptr, nullptr, nullptr, 0);
    // layer 3: h2 -> out = 0.25*(emb + x1 + x2 + x3), fused
    spmm_h_kernel<<<grid_spmm, TB>>>(h2, nullptr, emb, h1, h2, out, 1);
}

// round 17
// speedup vs baseline: 1.1592x; 1.1592x over previous
#include <cuda_runtime.h>
#include <cuda_fp16.h>
#include <cstdint>

// LightGCN: 3 layers of SpMM + running-mean accumulator.
// N=400000 nodes, D=64, E=4000000 edges.
// out = (x0 + x1 + x2 + x3) / 4, x_{k+1} = A @ x_k (A sparse COO, fp32 vals)
//
// R14 structure (CSR build, emb->fp16, 8-threads/row SpMM, fused final mean)
// with the edge loop rewritten as a single ceil(deg/4) predicated-unroll loop:
// no serial singleton tail, 4 gathers in flight every step, no extra bytes.

#define NUM_NODES 400000
#define EMB_DIM   64
#define NELEM     (NUM_NODES * EMB_DIM)   // 25,600,000
#define MAX_EDGES 4000000
#define SCAN_BLK  512
#define NB_SCAN   ((NUM_NODES + SCAN_BLK - 1) / SCAN_BLK)   // 782

// fp16 buffers (51.2 MB each): h0 = emb_fp16, h1/h2 ping-pong
__device__ __half g_h0[NELEM];
__device__ __half g_h1[NELEM];
__device__ __half g_h2[NELEM];

// CSR scratch
__device__ int  g_cnt[NUM_NODES];
__device__ int  g_rowptr[NUM_NODES];
__device__ int  g_ofs[NUM_NODES];
__device__ int  g_part[1024];
__device__ int2 g_edge[MAX_EDGES];     // {col, val_bits}
__device__ int  g_is64;

// ---------------------------------------------------------------------------
// dtype detect: int64 indices have all-zero high words (indices < 400000).
// ---------------------------------------------------------------------------
__global__ void detect_kernel(const unsigned int* __restrict__ raw) {
    __shared__ unsigned int s;
    if (threadIdx.x == 0) s = 0u;
    __syncthreads();
    unsigned int acc = 0u;
    for (int i = threadIdx.x; i < 1024; i += blockDim.x)
        acc |= raw[2 * i + 1];
    atomicOr(&s, acc);
    __syncthreads();
    if (threadIdx.x == 0) g_is64 = (s == 0u) ? 1 : 0;
}

__global__ void zero_cnt_kernel() {
    int i = blockIdx.x * blockDim.x + threadIdx.x;
    if (i < NUM_NODES) g_cnt[i] = 0;
}

__global__ void hist_kernel(const unsigned int* __restrict__ row_raw,
                            int n_edges) {
    int e = blockIdx.x * blockDim.x + threadIdx.x;
    if (e >= n_edges) return;
    int idx = g_is64 ? (2 * e) : e;
    atomicAdd(&g_cnt[(int)row_raw[idx]], 1);
}

// ---------------------------------------------------------------------------
// two-level exclusive scan of g_cnt -> g_rowptr (and g_ofs copy)
// ---------------------------------------------------------------------------
__global__ void scanA_kernel() {
    __shared__ int sh[SCAN_BLK];
    int tid = threadIdx.x;
    int gid = blockIdx.x * SCAN_BLK + tid;
    int v = (gid < NUM_NODES) ? g_cnt[gid] : 0;
    sh[tid] = v;
    __syncthreads();
    for (int off = 1; off < SCAN_BLK; off <<= 1) {
        int t = (tid >= off) ? sh[tid - off] : 0;
        __syncthreads();
        if (tid >= off) sh[tid] += t;
        __syncthreads();
    }
    if (gid < NUM_NODES) g_rowptr[gid] = sh[tid] - v;
    if (tid == SCAN_BLK - 1) g_part[blockIdx.x] = sh[tid];
}

__global__ void scanB_kernel() {
    __shared__ int sh[1024];
    int tid = threadIdx.x;
    int v = (tid < NB_SCAN) ? g_part[tid] : 0;
    sh[tid] = v;
    __syncthreads();
    for (int off = 1; off < 1024; off <<= 1) {
        int t = (tid >= off) ? sh[tid - off] : 0;
        __syncthreads();
        if (tid >= off) sh[tid] += t;
        __syncthreads();
    }
    if (tid < NB_SCAN) g_part[tid] = sh[tid] - v;
}

__global__ void scanC_kernel() {
    int i = blockIdx.x * blockDim.x + threadIdx.x;
    if (i >= NUM_NODES) return;
    int rp = g_rowptr[i] + g_part[i / SCAN_BLK];
    g_rowptr[i] = rp;
    g_ofs[i]    = rp;
}

__global__ void scatter_kernel(const unsigned int* __restrict__ row_raw,
                               const unsigned int* __restrict__ col_raw,
                               const float* __restrict__ val,
                               int n_edges) {
    int e = blockIdx.x * blockDim.x + threadIdx.x;
    if (e >= n_edges) return;
    int idx = g_is64 ? (2 * e) : e;
    int r = (int)row_raw[idx];
    int c = (int)col_raw[idx];
    int pos = atomicAdd(&g_ofs[r], 1);
    g_edge[pos] = make_int2(c, __float_as_int(val[e]));
}

// ---------------------------------------------------------------------------
// emb fp32 -> fp16 conversion, 8 floats per thread, float4 I/O
// ---------------------------------------------------------------------------
__global__ void conv_kernel(const float4* __restrict__ src,
                            float4* __restrict__ dst) {   // dst = half buffer
    int i = blockIdx.x * blockDim.x + threadIdx.x;        // 8-float chunk idx
    if (i >= NELEM / 8) return;
    float4 a = src[2 * i];
    float4 b = src[2 * i + 1];
    float4 r;
    __half2* h = reinterpret_cast<__half2*>(&r);
    h[0] = __float22half2_rn(make_float2(a.x, a.y));
    h[1] = __float22half2_rn(make_float2(a.z, a.w));
    h[2] = __float22half2_rn(make_float2(b.x, b.y));
    h[3] = __float22half2_rn(make_float2(b.z, b.w));
    dst[i] = r;
}

// ---------------------------------------------------------------------------
// helpers
// ---------------------------------------------------------------------------
__device__ __forceinline__ float4 pack8h(const float* a) {
    float4 r;
    __half2* h = reinterpret_cast<__half2*>(&r);
    h[0] = __float22half2_rn(make_float2(a[0], a[1]));
    h[1] = __float22half2_rn(make_float2(a[2], a[3]));
    h[2] = __float22half2_rn(make_float2(a[4], a[5]));
    h[3] = __float22half2_rn(make_float2(a[6], a[7]));
    return r;
}

__device__ __forceinline__ void accum8h(float* a, float4 x, float v) {
    const __half2* h = reinterpret_cast<const __half2*>(&x);
#pragma unroll
    for (int j = 0; j < 4; j++) {
        float2 f = __half22float2(h[j]);
        a[2 * j]     = fmaf(v, f.x, a[2 * j]);
        a[2 * j + 1] = fmaf(v, f.y, a[2 * j + 1]);
    }
}

// ---------------------------------------------------------------------------
// fp16-gather SpMM: 8 threads/row, 8 dims (1 float4 of halves) per lane.
// Single predicated unroll-x4 loop: ceil(deg/4) steps, 4 gathers in flight
// every step, predicated-off loads fetch nothing, OOB slots contribute v=0.
// mode 0: dst = acc (fp16)
// mode 1: out = 0.25*(emb_fp32 + x1 + x2 + acc)   (fused final mean)
// ---------------------------------------------------------------------------
__global__ void __launch_bounds__(256)
spmm_h_kernel(const __half* __restrict__ src,
              __half* __restrict__ dst,
              const float* __restrict__ emb,
              const __half* __restrict__ x1,
              const __half* __restrict__ x2,
              float* __restrict__ out,
              int final_mode) {
    int t = blockIdx.x * blockDim.x + threadIdx.x;
    int r = t >> 3;
    if (r >= NUM_NODES) return;
    int sub = t & 7;

    int start = g_rowptr[r];   // 8 lanes same addr -> broadcast
    int deg   = g_cnt[r];

    float a[8];
#pragma unroll
    for (int j = 0; j < 8; j++) a[j] = 0.f;

    const float4* s4 = reinterpret_cast<const float4*>(src);  // 8 halves each
    const float4 z4 = make_float4(0.f, 0.f, 0.f, 0.f);

    for (int i = 0; i < deg; i += 4) {
        int rem = deg - i;
        int2 e0 = __ldg(&g_edge[start + i]);
        int2 e1 = make_int2(0, 0), e2 = make_int2(0, 0), e3 = make_int2(0, 0);
        if (rem > 1) e1 = __ldg(&g_edge[start + i + 1]);
        if (rem > 2) e2 = __ldg(&g_edge[start + i + 2]);
        if (rem > 3) e3 = __ldg(&g_edge[start + i + 3]);

        float4 x0 = __ldg(s4 + (((size_t)e0.x) << 3) + sub);
        float4 x1v = z4, x2v = z4, x3v = z4;
        if (rem > 1) x1v = __ldg(s4 + (((size_t)e1.x) << 3) + sub);
        if (rem > 2) x2v = __ldg(s4 + (((size_t)e2.x) << 3) + sub);
        if (rem > 3) x3v = __ldg(s4 + (((size_t)e3.x) << 3) + sub);

        accum8h(a, x0,  __int_as_float(e0.y));
        accum8h(a, x1v, __int_as_float(e1.y));   // e1.y==0 -> v=0 when OOB
        accum8h(a, x2v, __int_as_float(e2.y));
        accum8h(a, x3v, __int_as_float(e3.y));
    }

    size_t hofs = ((size_t)r << 3) + sub;        // float4 index, half buffers
    if (!final_mode) {
        reinterpret_cast<float4*>(dst)[hofs] = pack8h(a);
    } else {
        size_t fofs = ((size_t)r << 4) + (sub << 1);  // float4 index, fp32
        const float4* E = reinterpret_cast<const float4*>(emb);
        float4 e0 = __ldg(E + fofs), e1 = __ldg(E + fofs + 1);

        float u[8], w[8];
        {
            float4 xh = __ldg(reinterpret_cast<const float4*>(x1) + hofs);
            const __half2* h = reinterpret_cast<const __half2*>(&xh);
#pragma unroll
            for (int j = 0; j < 4; j++) {
                float2 f = __half22float2(h[j]);
                u[2*j] = f.x; u[2*j+1] = f.y;
            }
        }
        {
            float4 xh = __ldg(reinterpret_cast<const float4*>(x2) + hofs);
            const __half2* h = reinterpret_cast<const __half2*>(&xh);
#pragma unroll
            for (int j = 0; j < 4; j++) {
                float2 f = __half22float2(h[j]);
                w[2*j] = f.x; w[2*j+1] = f.y;
            }
        }

        float4 r0, r1;
        r0.x = 0.25f * (e0.x + u[0] + w[0] + a[0]);
        r0.y = 0.25f * (e0.y + u[1] + w[1] + a[1]);
        r0.z = 0.25f * (e0.z + u[2] + w[2] + a[2]);
        r0.w = 0.25f * (e0.w + u[3] + w[3] + a[3]);
        r1.x = 0.25f * (e1.x + u[4] + w[4] + a[4]);
        r1.y = 0.25f * (e1.y + u[5] + w[5] + a[5]);
        r1.z = 0.25f * (e1.z + u[6] + w[6] + a[6]);
        r1.w = 0.25f * (e1.w + u[7] + w[7] + a[7]);
        reinterpret_cast<float4*>(out)[fofs]     = r0;
        reinterpret_cast<float4*>(out)[fofs + 1] = r1;
    }
}

// ---------------------------------------------------------------------------
// launch
// ---------------------------------------------------------------------------
extern "C" void kernel_launch(void* const* d_in, const int* in_sizes, int n_in,
                              void* d_out, int out_size) {
    // Order-robust binding: embedding is the unique input with NELEM elements;
    // the remaining three, in original order, are row, col, val.
    int emb_idx = -1;
    for (int i = 0; i < n_in; i++)
        if (in_sizes[i] == NELEM) { emb_idx = i; break; }
    if (emb_idx < 0) emb_idx = 0;

    int others[3]; int k = 0;
    for (int i = 0; i < n_in && k < 3; i++)
        if (i != emb_idx) others[k++] = i;

    const float*        emb     = (const float*)d_in[emb_idx];
    const unsigned int* row_raw = (const unsigned int*)d_in[others[0]];
    const unsigned int* col_raw = (const unsigned int*)d_in[others[1]];
    const float*        val     = (const float*)d_in[others[2]];
    float*              out     = (float*)d_out;
    const int n_edges = in_sizes[others[0]];

    __half *h0 = nullptr, *h1 = nullptr, *h2 = nullptr;
    cudaGetSymbolAddress((void**)&h0, g_h0);
    cudaGetSymbolAddress((void**)&h1, g_h1);
    cudaGetSymbolAddress((void**)&h2, g_h2);

    const int TB = 256;
    const int grid_edges = (n_edges + TB - 1) / TB;
    const int grid_nodes = (NUM_NODES + TB - 1) / TB;
    const int grid_conv  = (NELEM / 8 + TB - 1) / TB;
    const int grid_spmm  = (NUM_NODES * 8 + TB - 1) / TB;

    // ---- CSR build + emb fp16 conversion ----
    detect_kernel<<<1, 256>>>(row_raw);
    zero_cnt_kernel<<<grid_nodes, TB>>>();
    hist_kernel<<<grid_edges, TB>>>(row_raw, n_edges);
    conv_kernel<<<grid_conv, TB>>>((const float4*)emb, (float4*)h0);
    scanA_kernel<<<NB_SCAN, SCAN_BLK>>>();
    scanB_kernel<<<1, 1024>>>();
    scanC_kernel<<<grid_nodes, TB>>>();
    scatter_kernel<<<grid_edges, TB>>>(row_raw, col_raw, val, n_edges);

    // ---- 3 propagation layers (8 threads/row, fp16 gathers) ----
    // layer 1: h0 -> h1
    spmm_h_kernel<<<grid_spmm, TB>>>(h0, h1, nullptr, nullptr, nullptr, nullptr, 0);
    // layer 2: h1 -> h2
    spmm_h_kernel<<<grid_spmm, TB>>>(h1, h2, nullptr, nullptr, nullptr, nullptr, 0);
    // layer 3: h2 -> out = 0.25*(emb + x1 + x2 + x3), fused
    spmm_h_kernel<<<grid_spmm, TB>>>(h2, nullptr, emb, h1, h2, out, 1);
}